// round 4
// baseline (speedup 1.0000x reference)
#include <cuda_runtime.h>
#include <cuda_bf16.h>
#include <mma.h>
#include <math.h>

using namespace nvcuda;

// Problem shape (fixed): T=256, B=64, D=H=1024
#define TT 256
#define BB 64
#define HH 1024
#define NG 4096      // 4*H
#define TBm 16384    // T*B

// ---------------- scratch (device globals: allocation-free rule) -------------
__device__ float g_zx[(size_t)TBm * NG];     // 256 MB: x-projection for current layer
__device__ float g_hall[(size_t)TBm * HH];   // 64 MB: layer-0 hidden sequence
__device__ float g_c[BB * HH];               // cell state (in-place per layer)
__device__ __nv_bfloat16 g_hh[2][BB * HH];   // ping-pong h hi plane
__device__ __nv_bfloat16 g_hl[2][BB * HH];   // ping-pong h lo plane
__device__ __nv_bfloat16 g_wph[(size_t)HH * NG];  // packed recurrent W hi (8 MB)
__device__ __nv_bfloat16 g_wpl[(size_t)HH * NG];  // packed recurrent W lo (8 MB)

// ---------------- helpers ----------------------------------------------------
__device__ __forceinline__ void split_bf16(float x, __nv_bfloat16& hi, __nv_bfloat16& lo) {
    hi = __float2bfloat16(x);
    lo = __float2bfloat16(x - __bfloat162float(hi));
}
__device__ __forceinline__ float sigmoidf_(float x) { return 1.0f / (1.0f + expf(-x)); }

__device__ __forceinline__ void cpa16(void* dst, const void* src) {
    unsigned d = (unsigned)__cvta_generic_to_shared(dst);
    asm volatile("cp.async.cg.shared.global [%0], [%1], 16;" :: "r"(d), "l"(src));
}

__global__ void init_state_kernel(float* c, __nv_bfloat16* hh, __nv_bfloat16* hl) {
    int i = blockIdx.x * blockDim.x + threadIdx.x;
    if (i < BB * HH) {
        c[i] = 0.0f;
        hh[i] = __float2bfloat16(0.0f);
        hl[i] = __float2bfloat16(0.0f);
    }
}

// Pack recurrent half of W [rows 1024..2047, 4096] into per-CTA tile order:
// out[((c*1024 + k)*64) + g*16 + j] = W[1024+k][g*1024 + c*16 + j], hi/lo planes.
__global__ void prep_w_kernel(const float* __restrict__ W,
                              __nv_bfloat16* __restrict__ hi,
                              __nv_bfloat16* __restrict__ lo) {
    for (size_t i = (size_t)blockIdx.x * blockDim.x + threadIdx.x;
         i < (size_t)HH * NG; i += (size_t)gridDim.x * blockDim.x) {
        int k = (int)(i >> 12);
        int col = (int)(i & 4095);
        int g = col >> 10, h = col & 1023;
        int c = h >> 4, j = h & 15;
        float v = W[(size_t)(HH + k) * NG + col];
        size_t o = ((size_t)c * HH + k) * 64 + g * 16 + j;
        __nv_bfloat16 vh, vl;
        split_bf16(v, vh, vl);
        hi[o] = vh;
        lo[o] = vl;
    }
}

// ---------------- big input-projection GEMM ----------------------------------
#define GBM 128
#define GBN 128
#define GBK 32

__global__ __launch_bounds__(256) void gemm_x_kernel(
    const float* __restrict__ A, const float* __restrict__ W,
    float* __restrict__ Z)
{
    __shared__ __nv_bfloat16 Ah[GBM][GBK + 8];
    __shared__ __nv_bfloat16 Al[GBM][GBK + 8];
    __shared__ __nv_bfloat16 Bh[GBK][GBN + 8];
    __shared__ __nv_bfloat16 Bl[GBK][GBN + 8];

    const int bm = blockIdx.y * GBM;
    const int bn = blockIdx.x * GBN;
    const int tid = threadIdx.x;
    const int warp = tid >> 5;
    const int wm = (warp >> 2) * 64;
    const int wn = (warp & 3) * 32;

    wmma::fragment<wmma::accumulator, 16, 16, 16, float> acc[4][2];
#pragma unroll
    for (int i = 0; i < 4; ++i)
#pragma unroll
        for (int j = 0; j < 2; ++j)
            wmma::fill_fragment(acc[i][j], 0.0f);

    for (int kb = 0; kb < HH; kb += GBK) {
#pragma unroll
        for (int i = 0; i < 4; ++i) {
            int q = tid + i * 256;
            int r = q >> 3, c = (q & 7) * 4;
            float4 v = *(const float4*)(A + (size_t)(bm + r) * HH + kb + c);
            split_bf16(v.x, Ah[r][c + 0], Al[r][c + 0]);
            split_bf16(v.y, Ah[r][c + 1], Al[r][c + 1]);
            split_bf16(v.z, Ah[r][c + 2], Al[r][c + 2]);
            split_bf16(v.w, Ah[r][c + 3], Al[r][c + 3]);
        }
#pragma unroll
        for (int i = 0; i < 4; ++i) {
            int q = tid + i * 256;
            int r = q >> 5, c = (q & 31) * 4;
            float4 v = *(const float4*)(W + (size_t)(kb + r) * NG + bn + c);
            split_bf16(v.x, Bh[r][c + 0], Bl[r][c + 0]);
            split_bf16(v.y, Bh[r][c + 1], Bl[r][c + 1]);
            split_bf16(v.z, Bh[r][c + 2], Bl[r][c + 2]);
            split_bf16(v.w, Bh[r][c + 3], Bl[r][c + 3]);
        }
        __syncthreads();

#pragma unroll
        for (int kk = 0; kk < GBK; kk += 16) {
            wmma::fragment<wmma::matrix_a, 16, 16, 16, __nv_bfloat16, wmma::row_major> ah[4], al[4];
            wmma::fragment<wmma::matrix_b, 16, 16, 16, __nv_bfloat16, wmma::row_major> bh[2], bl[2];
#pragma unroll
            for (int i = 0; i < 4; ++i) {
                wmma::load_matrix_sync(ah[i], &Ah[wm + 16 * i][kk], GBK + 8);
                wmma::load_matrix_sync(al[i], &Al[wm + 16 * i][kk], GBK + 8);
            }
#pragma unroll
            for (int j = 0; j < 2; ++j) {
                wmma::load_matrix_sync(bh[j], &Bh[kk][wn + 16 * j], GBN + 8);
                wmma::load_matrix_sync(bl[j], &Bl[kk][wn + 16 * j], GBN + 8);
            }
#pragma unroll
            for (int i = 0; i < 4; ++i)
#pragma unroll
                for (int j = 0; j < 2; ++j) {
                    wmma::mma_sync(acc[i][j], ah[i], bh[j], acc[i][j]);
                    wmma::mma_sync(acc[i][j], ah[i], bl[j], acc[i][j]);
                    wmma::mma_sync(acc[i][j], al[i], bh[j], acc[i][j]);
                }
        }
        __syncthreads();
    }

#pragma unroll
    for (int i = 0; i < 4; ++i)
#pragma unroll
        for (int j = 0; j < 2; ++j)
            wmma::store_matrix_sync(Z + (size_t)(bm + wm + 16 * i) * NG + bn + wn + 16 * j,
                                    acc[i][j], NG, wmma::mem_row_major);
}

// ---------------- fused recurrent step (pipelined) ----------------------------
// 64 CTAs x 256 threads. CTA c owns hidden cols [c*16, c*16+16) across all 4
// gates (64 z-cols). 6-stage cp.async pipeline over K=1024 in KB=32 chunks.
// Warp w: gate g=w>>1, m-half mh=w&1 (rows mh*32..mh*32+32).
#define STAGES 6
#define SKB 32

struct StepSmem {
    __nv_bfloat16 wh[STAGES][SKB][64];   // 24 KB
    __nv_bfloat16 wl[STAGES][SKB][64];   // 24 KB
    __nv_bfloat16 hh[STAGES][BB][SKB];   // 24 KB
    __nv_bfloat16 hl[STAGES][BB][SKB];   // 24 KB
    float zxs[BB][64];                   // 16 KB
    float cs[BB][16];                    //  4 KB
    float zs[4][BB][16];                 // 16 KB
};

__global__ __launch_bounds__(256) void lstm_step_kernel(
    const float* __restrict__ zx,            // [64,4096] this t (x-projection)
    const __nv_bfloat16* __restrict__ wph,   // packed Wh hi
    const __nv_bfloat16* __restrict__ wpl,   // packed Wh lo
    const float* __restrict__ bias,          // [4096]
    const __nv_bfloat16* __restrict__ hh_in, // [64,1024] prev h hi
    const __nv_bfloat16* __restrict__ hl_in, // [64,1024] prev h lo
    __nv_bfloat16* __restrict__ hh_out,
    __nv_bfloat16* __restrict__ hl_out,
    float* __restrict__ cst,                 // [64,1024] cell (in/out)
    float* __restrict__ hout)                // [64,1024] new h fp32
{
    extern __shared__ unsigned char smem_raw[];
    StepSmem* S = (StepSmem*)smem_raw;

    const int tid = threadIdx.x;
    const int warp = tid >> 5;
    const int cblk = blockIdx.x;     // 0..63
    const int nj = cblk * 16;
    const int g = warp >> 1, mh = warp & 1;

    // ---- stage loader: W tile [SKB][64] + h tile [64][SKB], one chunk set/thread
    auto load_stage = [&](int s, int it) {
        int kb = it * SKB;
        {   // W planes: 32 rows x 128B = 256 chunks each
            int row = tid >> 3, off = tid & 7;
            const char* srch = (const char*)(wph + ((size_t)cblk * HH + kb + row) * 64) + off * 16;
            const char* srcl = (const char*)(wpl + ((size_t)cblk * HH + kb + row) * 64) + off * 16;
            cpa16((char*)&S->wh[s][row][0] + off * 16, srch);
            cpa16((char*)&S->wl[s][row][0] + off * 16, srcl);
        }
        {   // h planes: 64 rows x 64B = 256 chunks each
            int r = tid >> 2, off = tid & 3;
            const char* srch = (const char*)(hh_in + (size_t)r * HH + kb) + off * 16;
            const char* srcl = (const char*)(hl_in + (size_t)r * HH + kb) + off * 16;
            cpa16((char*)&S->hh[s][r][0] + off * 16, srch);
            cpa16((char*)&S->hl[s][r][0] + off * 16, srcl);
        }
    };

    // ---- group 0: zx + c prefetch + stage 0
    {
#pragma unroll
        for (int i = 0; i < 4; ++i) {       // zx: [64][4 gates][16] fp32
            int q = tid + i * 256;
            int r = q >> 4, gg = (q >> 2) & 3, off = q & 3;
            cpa16((char*)&S->zxs[r][gg * 16] + off * 16,
                  (const char*)(zx + (size_t)r * NG + gg * HH + nj) + off * 16);
        }
        {   // c: 64 rows x 64B
            int r = tid >> 2, off = tid & 3;
            cpa16((char*)&S->cs[r][0] + off * 16,
                  (const char*)(cst + (size_t)r * HH + nj) + off * 16);
        }
        load_stage(0, 0);
        asm volatile("cp.async.commit_group;" ::: "memory");
    }
    // ---- preload stages 1..4
#pragma unroll
    for (int s = 1; s < STAGES - 1; ++s) {
        load_stage(s, s);
        asm volatile("cp.async.commit_group;" ::: "memory");
    }

    wmma::fragment<wmma::accumulator, 16, 16, 16, float> acc[2];
    wmma::fill_fragment(acc[0], 0.0f);
    wmma::fill_fragment(acc[1], 0.0f);

    const int NIT = HH / SKB;   // 32
    for (int it = 0; it < NIT; ++it) {
        asm volatile("cp.async.wait_group 4;" ::: "memory");
        __syncthreads();
        int cur = it % STAGES;

#pragma unroll
        for (int kk = 0; kk < SKB; kk += 16) {
            wmma::fragment<wmma::matrix_b, 16, 16, 16, __nv_bfloat16, wmma::row_major> bh, bl;
            wmma::load_matrix_sync(bh, &S->wh[cur][kk][g * 16], 64);
            wmma::load_matrix_sync(bl, &S->wl[cur][kk][g * 16], 64);
#pragma unroll
            for (int i = 0; i < 2; ++i) {
                wmma::fragment<wmma::matrix_a, 16, 16, 16, __nv_bfloat16, wmma::row_major> ah, al;
                wmma::load_matrix_sync(ah, &S->hh[cur][mh * 32 + i * 16][kk], SKB);
                wmma::load_matrix_sync(al, &S->hl[cur][mh * 32 + i * 16][kk], SKB);
                wmma::mma_sync(acc[i], ah, bh, acc[i]);
                wmma::mma_sync(acc[i], ah, bl, acc[i]);
                wmma::mma_sync(acc[i], al, bh, acc[i]);
            }
        }

        // refill the stage consumed last iteration (safe: everyone passed the
        // top-of-iteration barrier, so nobody is still reading it)
        if (it + STAGES - 1 < NIT)
            load_stage((it + STAGES - 1) % STAGES, it + STAGES - 1);
        asm volatile("cp.async.commit_group;" ::: "memory");
    }

    // ---- park recurrent z, then fuse gates
    wmma::store_matrix_sync(&S->zs[g][mh * 32][0], acc[0], 16, wmma::mem_row_major);
    wmma::store_matrix_sync(&S->zs[g][mh * 32 + 16][0], acc[1], 16, wmma::mem_row_major);
    __syncthreads();

#pragma unroll
    for (int e = tid; e < BB * 16; e += 256) {
        int r = e >> 4, col = e & 15;
        int gc = nj + col;
        float zi = S->zs[0][r][col] + S->zxs[r][col]      + bias[gc];
        float zj = S->zs[1][r][col] + S->zxs[r][16 + col] + bias[HH + gc];
        float zf = S->zs[2][r][col] + S->zxs[r][32 + col] + bias[2 * HH + gc];
        float zo = S->zs[3][r][col] + S->zxs[r][48 + col] + bias[3 * HH + gc];
        float cold = S->cs[r][col];
        float nc = cold * sigmoidf_(zf + 1.0f) + sigmoidf_(zi) * tanhf(zj);
        float nh = tanhf(nc) * sigmoidf_(zo);
        size_t o = (size_t)r * HH + gc;
        cst[o] = nc;
        hout[o] = nh;
        __nv_bfloat16 hi, lo;
        split_bf16(nh, hi, lo);
        hh_out[o] = hi;
        hl_out[o] = lo;
    }
}

// ---------------- launch ------------------------------------------------------
extern "C" void kernel_launch(void* const* d_in, const int* in_sizes, int n_in,
                              void* d_out, int out_size)
{
    const float* x  = (const float*)d_in[0];   // [256,64,1024]
    const float* W0 = (const float*)d_in[1];   // [2048,4096]
    const float* b0 = (const float*)d_in[2];   // [4096]
    const float* W1 = (const float*)d_in[3];   // [2048,4096]
    const float* b1 = (const float*)d_in[4];   // [4096]
    float* out = (float*)d_out;                // [256,64,1024]

    float *zx, *hall, *cst;
    __nv_bfloat16 *hhb, *hlb, *wph, *wpl;
    cudaGetSymbolAddress((void**)&zx,   g_zx);
    cudaGetSymbolAddress((void**)&hall, g_hall);
    cudaGetSymbolAddress((void**)&cst,  g_c);
    cudaGetSymbolAddress((void**)&hhb,  g_hh);
    cudaGetSymbolAddress((void**)&hlb,  g_hl);
    cudaGetSymbolAddress((void**)&wph,  g_wph);
    cudaGetSymbolAddress((void**)&wpl,  g_wpl);

    const int step_smem = (int)sizeof(StepSmem);
    cudaFuncSetAttribute(lstm_step_kernel,
                         cudaFuncAttributeMaxDynamicSharedMemorySize, step_smem);

    const dim3 ggrid(NG / GBN, TBm / GBM);   // (32, 128)

    // ---- layer 0 ----
    prep_w_kernel<<<2048, 256>>>(W0, wph, wpl);
    init_state_kernel<<<(BB * HH + 255) / 256, 256>>>(cst, hhb, hlb);
    gemm_x_kernel<<<ggrid, 256>>>(x, W0, zx);
    for (int t = 0; t < TT; ++t) {
        int rb = t & 1, wb = (t + 1) & 1;
        lstm_step_kernel<<<HH / 16, 256, step_smem>>>(
            zx + (size_t)t * BB * NG, wph, wpl, b0,
            hhb + (size_t)rb * BB * HH, hlb + (size_t)rb * BB * HH,
            hhb + (size_t)wb * BB * HH, hlb + (size_t)wb * BB * HH,
            cst, hall + (size_t)t * BB * HH);
    }

    // ---- layer 1 ----
    prep_w_kernel<<<2048, 256>>>(W1, wph, wpl);
    init_state_kernel<<<(BB * HH + 255) / 256, 256>>>(cst, hhb, hlb);
    gemm_x_kernel<<<ggrid, 256>>>(hall, W1, zx);
    for (int t = 0; t < TT; ++t) {
        int rb = t & 1, wb = (t + 1) & 1;
        lstm_step_kernel<<<HH / 16, 256, step_smem>>>(
            zx + (size_t)t * BB * NG, wph, wpl, b1,
            hhb + (size_t)rb * BB * HH, hlb + (size_t)rb * BB * HH,
            hhb + (size_t)wb * BB * HH, hlb + (size_t)wb * BB * HH,
            cst, out + (size_t)t * BB * HH);
    }
}

// round 5
// speedup vs baseline: 1.7400x; 1.7400x over previous
#include <cuda_runtime.h>
#include <cuda_bf16.h>
#include <mma.h>
#include <math.h>

using namespace nvcuda;

// Problem shape (fixed): T=256, B=64, D=H=1024
#define TT 256
#define BB 64
#define HH 1024
#define NG 4096      // 4*H
#define TBm 16384    // T*B
#define PKCTA 128    // persistent CTAs (1 per SM, all co-resident)

// ---------------- scratch (device globals: allocation-free rule) -------------
__device__ float g_zx[(size_t)TBm * NG];      // 256 MB: x-projection (gemm out)
__device__ float g_zxp[(size_t)TBm * NG];     // 256 MB: repacked zx (+bias)
__device__ float g_hall[(size_t)TBm * HH];    // 64 MB: layer-0 hidden sequence
__device__ __nv_bfloat16 g_hh[2][BB * HH];    // ping-pong h hi plane
__device__ __nv_bfloat16 g_hl[2][BB * HH];    // ping-pong h lo plane
__device__ __nv_bfloat16 g_wph[(size_t)HH * NG];   // packed recurrent W hi (8 MB)
__device__ __nv_bfloat16 g_wpl[(size_t)HH * NG];   // packed recurrent W lo (8 MB)
__device__ int g_bar[2 * TT];                 // grid barrier counters

// ---------------- helpers ----------------------------------------------------
__device__ __forceinline__ void split_bf16(float x, __nv_bfloat16& hi, __nv_bfloat16& lo) {
    hi = __float2bfloat16(x);
    lo = __float2bfloat16(x - __bfloat162float(hi));
}
__device__ __forceinline__ float sigmoidf_(float x) { return 1.0f / (1.0f + expf(-x)); }

__device__ __forceinline__ void cpa16(void* dst, const void* src) {
    unsigned d = (unsigned)__cvta_generic_to_shared(dst);
    asm volatile("cp.async.cg.shared.global [%0], [%1], 16;" :: "r"(d), "l"(src));
}

__global__ void init_state_kernel(__nv_bfloat16* hh, __nv_bfloat16* hl, int* bar) {
    int i = blockIdx.x * blockDim.x + threadIdx.x;
    if (i < 2 * BB * HH) {                    // zero both ping-pong buffers
        hh[i] = __float2bfloat16(0.0f);
        hl[i] = __float2bfloat16(0.0f);
    }
    if (i < TT) bar[i] = 0;
}

// Pack recurrent half of W into per-CTA contiguous slices:
// wp[(c*1024 + k)*32 + g*8 + j] = W[1024+k][g*1024 + c*8 + j]  (hi/lo planes)
__global__ void prep_w_kernel(const float* __restrict__ W,
                              __nv_bfloat16* __restrict__ hi,
                              __nv_bfloat16* __restrict__ lo) {
    for (size_t o = (size_t)blockIdx.x * blockDim.x + threadIdx.x;
         o < (size_t)HH * NG; o += (size_t)gridDim.x * blockDim.x) {
        int col = (int)(o & 31);
        int k   = (int)((o >> 5) & 1023);
        int c   = (int)(o >> 15);
        int g = col >> 3, j = col & 7;
        float v = W[(size_t)(HH + k) * NG + g * HH + c * 8 + j];
        __nv_bfloat16 vh, vl;
        split_bf16(v, vh, vl);
        hi[o] = vh;
        lo[o] = vl;
    }
}

// Repack zx (+bias) into per-(t, CTA) contiguous 8KB blocks:
// zxp[((t*128 + c)*64 + row)*32 + g*8 + j] = zx[(t*64+row)*4096 + g*1024 + c*8 + j] + bias[...]
__global__ void repack_zx_kernel(const float* __restrict__ zx,
                                 const float* __restrict__ bias,
                                 float* __restrict__ zxp) {
    for (size_t o = (size_t)blockIdx.x * blockDim.x + threadIdx.x;
         o < (size_t)TBm * NG; o += (size_t)gridDim.x * blockDim.x) {
        int col = (int)(o & 31);
        int row = (int)((o >> 5) & 63);
        int c   = (int)((o >> 11) & 127);
        int t   = (int)(o >> 18);
        int g = col >> 3, j = col & 7;
        int n = g * HH + c * 8 + j;
        zxp[o] = zx[((size_t)t * BB + row) * NG + n] + bias[n];
    }
}

// ---------------- big input-projection GEMM ----------------------------------
#define GBM 128
#define GBN 128
#define GBK 32

__global__ __launch_bounds__(256) void gemm_x_kernel(
    const float* __restrict__ A, const float* __restrict__ W,
    float* __restrict__ Z)
{
    __shared__ __nv_bfloat16 Ah[GBM][GBK + 8];
    __shared__ __nv_bfloat16 Al[GBM][GBK + 8];
    __shared__ __nv_bfloat16 Bh[GBK][GBN + 8];
    __shared__ __nv_bfloat16 Bl[GBK][GBN + 8];

    const int bm = blockIdx.y * GBM;
    const int bn = blockIdx.x * GBN;
    const int tid = threadIdx.x;
    const int warp = tid >> 5;
    const int wm = (warp >> 2) * 64;
    const int wn = (warp & 3) * 32;

    wmma::fragment<wmma::accumulator, 16, 16, 16, float> acc[4][2];
#pragma unroll
    for (int i = 0; i < 4; ++i)
#pragma unroll
        for (int j = 0; j < 2; ++j)
            wmma::fill_fragment(acc[i][j], 0.0f);

    for (int kb = 0; kb < HH; kb += GBK) {
#pragma unroll
        for (int i = 0; i < 4; ++i) {
            int q = tid + i * 256;
            int r = q >> 3, c = (q & 7) * 4;
            float4 v = *(const float4*)(A + (size_t)(bm + r) * HH + kb + c);
            split_bf16(v.x, Ah[r][c + 0], Al[r][c + 0]);
            split_bf16(v.y, Ah[r][c + 1], Al[r][c + 1]);
            split_bf16(v.z, Ah[r][c + 2], Al[r][c + 2]);
            split_bf16(v.w, Ah[r][c + 3], Al[r][c + 3]);
        }
#pragma unroll
        for (int i = 0; i < 4; ++i) {
            int q = tid + i * 256;
            int r = q >> 5, c = (q & 31) * 4;
            float4 v = *(const float4*)(W + (size_t)(kb + r) * NG + bn + c);
            split_bf16(v.x, Bh[r][c + 0], Bl[r][c + 0]);
            split_bf16(v.y, Bh[r][c + 1], Bl[r][c + 1]);
            split_bf16(v.z, Bh[r][c + 2], Bl[r][c + 2]);
            split_bf16(v.w, Bh[r][c + 3], Bl[r][c + 3]);
        }
        __syncthreads();

#pragma unroll
        for (int kk = 0; kk < GBK; kk += 16) {
            wmma::fragment<wmma::matrix_a, 16, 16, 16, __nv_bfloat16, wmma::row_major> ah[4], al[4];
            wmma::fragment<wmma::matrix_b, 16, 16, 16, __nv_bfloat16, wmma::row_major> bh[2], bl[2];
#pragma unroll
            for (int i = 0; i < 4; ++i) {
                wmma::load_matrix_sync(ah[i], &Ah[wm + 16 * i][kk], GBK + 8);
                wmma::load_matrix_sync(al[i], &Al[wm + 16 * i][kk], GBK + 8);
            }
#pragma unroll
            for (int j = 0; j < 2; ++j) {
                wmma::load_matrix_sync(bh[j], &Bh[kk][wn + 16 * j], GBN + 8);
                wmma::load_matrix_sync(bl[j], &Bl[kk][wn + 16 * j], GBN + 8);
            }
#pragma unroll
            for (int i = 0; i < 4; ++i)
#pragma unroll
                for (int j = 0; j < 2; ++j) {
                    wmma::mma_sync(acc[i][j], ah[i], bh[j], acc[i][j]);
                    wmma::mma_sync(acc[i][j], ah[i], bl[j], acc[i][j]);
                    wmma::mma_sync(acc[i][j], al[i], bh[j], acc[i][j]);
                }
        }
        __syncthreads();
    }

#pragma unroll
    for (int i = 0; i < 4; ++i)
#pragma unroll
        for (int j = 0; j < 2; ++j)
            wmma::store_matrix_sync(Z + (size_t)(bm + wm + 16 * i) * NG + bn + wn + 16 * j,
                                    acc[i][j], NG, wmma::mem_row_major);
}

// ---------------- persistent recurrent kernel ---------------------------------
// 128 CTAs x 256 threads, one per SM, all 256 timesteps inside one launch.
// CTA c owns hidden cols [c*8, c*8+8) -> 32 z-cols (4 gates x 8, packed).
// W slice (1024 x 32, hi/lo bf16) resident in SMEM; c-state resident in SMEM.
// Per step: stream h (hi/lo) in 16 chunks of k=64 via 3-slot cp.async ring,
// 8 warps = 4 m-tiles x 2 k-halves, 3-pass bf16 MMA with 6 indep acc chains,
// epilogue fuses gates, writes h planes + fp32 h, grid-syncs via flag barrier.
#define CH 64        // k per chunk
#define NCH 16       // chunks per step
#define HST 72       // h smem stride (64+8): 144B rows, conflict-free, 16B aligned
#define WST 32       // W smem stride (no pad; minor ldsm conflicts acceptable)

struct PSmem {
    __nv_bfloat16 wh[HH][WST];        // 64 KB
    __nv_bfloat16 wl[HH][WST];        // 64 KB
    __nv_bfloat16 hh[3][BB][HST];     // 27 KB
    __nv_bfloat16 hl[3][BB][HST];     // 27 KB
    float zxs[BB][32];                // 8 KB
    float cs[BB][8];                  // 2 KB
    float zs[2][BB][32];              // 16 KB
};                                    // total 212992 B = 208 KB

__global__ __launch_bounds__(256) void lstm_persist_kernel(
    const float* __restrict__ zxp,           // [256][128][64][32] packed (+bias)
    const __nv_bfloat16* __restrict__ wph,   // packed Wh hi
    const __nv_bfloat16* __restrict__ wpl,   // packed Wh lo
    __nv_bfloat16* __restrict__ hhb,         // [2][64*1024] ping-pong hi
    __nv_bfloat16* __restrict__ hlb,         // [2][64*1024] ping-pong lo
    float* __restrict__ hout_all,            // [256][64][1024]
    int* __restrict__ bar)                   // [256]
{
    extern __shared__ unsigned char smem_raw[];
    PSmem* S = (PSmem*)smem_raw;

    const int tid  = threadIdx.x;
    const int warp = tid >> 5;
    const int cblk = blockIdx.x;             // 0..127
    const int mt   = warp & 3;               // m-tile (16 rows)
    const int kh   = warp >> 2;              // k-half (0/1)

    // ---- load W slice into SMEM once (1024 rows x 64B per plane) ----
    for (int i = tid; i < HH * 4; i += 256) {
        int row = i >> 2, off = (i & 3) * 8;   // 8 bf16 = 16B
        cpa16(&S->wh[row][off], wph + ((size_t)cblk * HH + row) * 32 + off);
        cpa16(&S->wl[row][off], wpl + ((size_t)cblk * HH + row) * 32 + off);
    }
    asm volatile("cp.async.commit_group;\ncp.async.wait_group 0;" ::: "memory");
    // ---- zero c-state ----
    for (int e = tid; e < BB * 8; e += 256) ((float*)S->cs)[e] = 0.0f;
    __syncthreads();

    auto load_chunk = [&](int slot, int ic, const __nv_bfloat16* hin_h,
                          const __nv_bfloat16* hin_l) {
        // 64 rows x 128B per plane = 512 x 16B chunks per plane
#pragma unroll
        for (int p = 0; p < 2; ++p) {
            int i = tid + p * 256;
            int r = i >> 3, off = (i & 7) * 8;
            cpa16(&S->hh[slot][r][off], hin_h + (size_t)r * HH + ic * CH + off);
            cpa16(&S->hl[slot][r][off], hin_l + (size_t)r * HH + ic * CH + off);
        }
    };

    for (int t = 0; t < TT; ++t) {
        const __nv_bfloat16* hin_h = hhb + (size_t)(t & 1) * BB * HH;
        const __nv_bfloat16* hin_l = hlb + (size_t)(t & 1) * BB * HH;
        __nv_bfloat16* hout_h = hhb + (size_t)((t + 1) & 1) * BB * HH;
        __nv_bfloat16* hout_l = hlb + (size_t)((t + 1) & 1) * BB * HH;

        // prefetch zx block (8KB) + chunk0 ; then chunk1
        {
            const float* zsrc = zxp + ((size_t)t * PKCTA + cblk) * (BB * 32);
#pragma unroll
            for (int p = 0; p < 2; ++p) {
                int i = tid + p * 256;
                cpa16(((char*)S->zxs) + i * 16, ((const char*)zsrc) + i * 16);
            }
            load_chunk(0, 0, hin_h, hin_l);
            asm volatile("cp.async.commit_group;" ::: "memory");
            load_chunk(1, 1, hin_h, hin_l);
            asm volatile("cp.async.commit_group;" ::: "memory");
        }

        wmma::fragment<wmma::accumulator, 16, 16, 16, float> acc[2][3];
#pragma unroll
        for (int nt = 0; nt < 2; ++nt)
#pragma unroll
            for (int p = 0; p < 3; ++p)
                wmma::fill_fragment(acc[nt][p], 0.0f);

        for (int ic = 0; ic < NCH; ++ic) {
            asm volatile("cp.async.wait_group 1;" ::: "memory");
            __syncthreads();
            int sl = ic % 3;

#pragma unroll
            for (int kk = 0; kk < 2; ++kk) {
                int kb = kh * 32 + kk * 16;              // k offset within chunk
                wmma::fragment<wmma::matrix_a, 16, 16, 16, __nv_bfloat16, wmma::row_major> ah, al;
                wmma::load_matrix_sync(ah, &S->hh[sl][mt * 16][kb], HST);
                wmma::load_matrix_sync(al, &S->hl[sl][mt * 16][kb], HST);
                int krow = ic * CH + kb;
#pragma unroll
                for (int nt = 0; nt < 2; ++nt) {
                    wmma::fragment<wmma::matrix_b, 16, 16, 16, __nv_bfloat16, wmma::row_major> bh, bl;
                    wmma::load_matrix_sync(bh, &S->wh[krow][nt * 16], WST);
                    wmma::load_matrix_sync(bl, &S->wl[krow][nt * 16], WST);
                    wmma::mma_sync(acc[nt][0], ah, bh, acc[nt][0]);
                    wmma::mma_sync(acc[nt][1], ah, bl, acc[nt][1]);
                    wmma::mma_sync(acc[nt][2], al, bh, acc[nt][2]);
                }
            }

            if (ic + 2 < NCH) load_chunk((ic + 2) % 3, ic + 2, hin_h, hin_l);
            asm volatile("cp.async.commit_group;" ::: "memory");
        }
        asm volatile("cp.async.wait_group 0;" ::: "memory");

        // ---- sum 3 passes, park partials ----
#pragma unroll
        for (int nt = 0; nt < 2; ++nt) {
#pragma unroll
            for (int e = 0; e < acc[nt][0].num_elements; ++e)
                acc[nt][0].x[e] += acc[nt][1].x[e] + acc[nt][2].x[e];
            wmma::store_matrix_sync(&S->zs[kh][mt * 16][nt * 16], acc[nt][0], 32,
                                    wmma::mem_row_major);
        }
        __syncthreads();

        // ---- gate fusion: 512 elements (64 rows x 8 hidden cols) ----
#pragma unroll
        for (int e = tid; e < BB * 8; e += 256) {
            int row = e & 63, j = e >> 6;
            float zi = S->zs[0][row][j]      + S->zs[1][row][j]      + S->zxs[row][j];
            float zj = S->zs[0][row][8 + j]  + S->zs[1][row][8 + j]  + S->zxs[row][8 + j];
            float zf = S->zs[0][row][16 + j] + S->zs[1][row][16 + j] + S->zxs[row][16 + j];
            float zo = S->zs[0][row][24 + j] + S->zs[1][row][24 + j] + S->zxs[row][24 + j];
            float cold = S->cs[row][j];
            float nc = cold * sigmoidf_(zf + 1.0f) + sigmoidf_(zi) * tanhf(zj);
            float nh = tanhf(nc) * sigmoidf_(zo);
            S->cs[row][j] = nc;
            size_t o = (size_t)row * HH + cblk * 8 + j;
            __nv_bfloat16 hi, lo;
            split_bf16(nh, hi, lo);
            hout_h[o] = hi;
            hout_l[o] = lo;
            hout_all[(size_t)t * BB * HH + o] = nh;
        }
        __syncthreads();

        // ---- grid barrier (release/acquire flag) ----
        if (tid == 0) {
            __threadfence();
            atomicAdd(&bar[t], 1);
            int v;
            do {
                asm volatile("ld.global.acquire.gpu.b32 %0, [%1];"
                             : "=r"(v) : "l"(bar + t) : "memory");
                if (v < PKCTA) __nanosleep(64);
            } while (v < PKCTA);
        }
        __syncthreads();
    }
}

// ---------------- launch ------------------------------------------------------
extern "C" void kernel_launch(void* const* d_in, const int* in_sizes, int n_in,
                              void* d_out, int out_size)
{
    const float* x  = (const float*)d_in[0];   // [256,64,1024]
    const float* W0 = (const float*)d_in[1];   // [2048,4096]
    const float* b0 = (const float*)d_in[2];   // [4096]
    const float* W1 = (const float*)d_in[3];   // [2048,4096]
    const float* b1 = (const float*)d_in[4];   // [4096]
    float* out = (float*)d_out;                // [256,64,1024]

    float *zx, *zxp, *hall;
    __nv_bfloat16 *hhb, *hlb, *wph, *wpl;
    int* bar;
    cudaGetSymbolAddress((void**)&zx,   g_zx);
    cudaGetSymbolAddress((void**)&zxp,  g_zxp);
    cudaGetSymbolAddress((void**)&hall, g_hall);
    cudaGetSymbolAddress((void**)&hhb,  g_hh);
    cudaGetSymbolAddress((void**)&hlb,  g_hl);
    cudaGetSymbolAddress((void**)&wph,  g_wph);
    cudaGetSymbolAddress((void**)&wpl,  g_wpl);
    cudaGetSymbolAddress((void**)&bar,  g_bar);

    const int psmem = (int)sizeof(PSmem);
    cudaFuncSetAttribute(lstm_persist_kernel,
                         cudaFuncAttributeMaxDynamicSharedMemorySize, psmem);

    const dim3 ggrid(NG / GBN, TBm / GBM);   // (32, 128)

    // ---- layer 0 ----
    prep_w_kernel<<<2048, 256>>>(W0, wph, wpl);
    init_state_kernel<<<(2 * BB * HH + 255) / 256, 256>>>(hhb, hlb, bar);
    gemm_x_kernel<<<ggrid, 256>>>(x, W0, zx);
    repack_zx_kernel<<<8192, 256>>>(zx, b0, zxp);
    lstm_persist_kernel<<<PKCTA, 256, psmem>>>(zxp, wph, wpl, hhb, hlb, hall, bar);

    // ---- layer 1 ----
    prep_w_kernel<<<2048, 256>>>(W1, wph, wpl);
    init_state_kernel<<<(2 * BB * HH + 255) / 256, 256>>>(hhb, hlb, bar + TT);
    gemm_x_kernel<<<ggrid, 256>>>(hall, W1, zx);
    repack_zx_kernel<<<8192, 256>>>(zx, b1, zxp);
    lstm_persist_kernel<<<PKCTA, 256, psmem>>>(zxp, wph, wpl, hhb, hlb, out, bar + TT);
}